// round 12
// baseline (speedup 1.0000x reference)
#include <cuda_runtime.h>
#include <cuda_bf16.h>
#include <cstdint>

// Problem constants
#define Dm 1024
#define Hn 16
#define HD 64
#define Bb 8
#define Ss 1024
#define M_ROWS (Bb * Ss)          // 8192

// Scratch (no runtime allocation allowed)
__device__ float g_q[(size_t)M_ROWS * Dm];        // 33.5 MB
__device__ float g_kv[(size_t)M_ROWS * 2 * Dm];   // 67 MB
__device__ float g_heads[(size_t)M_ROWS * Dm];    // 33.5 MB

// ===========================================================================
// Helpers
// ===========================================================================
#define MMA16816(c, a, b)                                                     \
    asm volatile("mma.sync.aligned.m16n8k16.row.col.f32.bf16.bf16.f32 "       \
        "{%0,%1,%2,%3}, {%4,%5,%6,%7}, {%8,%9}, {%0,%1,%2,%3};"               \
        : "+f"((c)[0]), "+f"((c)[1]), "+f"((c)[2]), "+f"((c)[3])              \
        : "r"((a)[0]), "r"((a)[1]), "r"((a)[2]), "r"((a)[3]),                 \
          "r"((b)[0]), "r"((b)[1]))

// fp32 pair -> (hi bf16 pair, lo bf16 pair) packed as uint32
__device__ __forceinline__ void split2(float x, float y, uint32_t& hi, uint32_t& lo) {
    __nv_bfloat16 hx = __float2bfloat16(x), hy = __float2bfloat16(y);
    __nv_bfloat16 lx = __float2bfloat16(x - __bfloat162float(hx));
    __nv_bfloat16 ly = __float2bfloat16(y - __bfloat162float(hy));
    hi = (uint32_t)__bfloat16_as_ushort(hx) | ((uint32_t)__bfloat16_as_ushort(hy) << 16);
    lo = (uint32_t)__bfloat16_as_ushort(lx) | ((uint32_t)__bfloat16_as_ushort(ly) << 16);
}

// ===========================================================================
// HMMA GEMM + bias, bf16x3 split (fp32-accurate): C[M,N] = A[M,K]@W[K,N]+bias
// CTA tile 128x64, K-chunk 32, 8 warps (4x2), warp tile 32x32.
//  - __launch_bounds__(256,2): <=128 regs -> 2 CTAs/SM -> 4 warps/SMSP
//    (R8 version was register-limited to 2 warps/SMSP; issue=20.9%).
//  - Register-staged loader: LDG chunk c+1 issued BEFORE compute(c),
//    convert+STS after -> L2 latency hidden under the MMAs.
// Smem pitch 36 elems (72 B): conflict-free scalar LDS for the m16n8k16
// thread map, 2-way worst case on stores.
// ===========================================================================
#define KC 32
#define PITCH 36
#define A_TILE_E (128 * PITCH)                 // 4608 bf16
#define B_TILE_E (64 * PITCH)                  // 2304 bf16
#define STAGE_E (2 * A_TILE_E + 2 * B_TILE_E)  // Ahi,Alo,Bhi,Blo = 13824
#define STAGE_B (STAGE_E * 2)                  // 27648 B
#define GEMM_SMEM (2 * STAGE_B)                // 55296 B

__global__ __launch_bounds__(256, 2)
void gemm_mma_kernel(const float* __restrict__ A, const float* __restrict__ W,
                     const float* __restrict__ bias, float* __restrict__ C,
                     int N, int K)
{
    extern __shared__ __nv_bfloat16 sm[];

    const int tid  = threadIdx.x;
    const int lane = tid & 31;
    const int warp = tid >> 5;
    const int g    = lane >> 2;        // row within 8-row block
    const int tig  = lane & 3;         // thread in group
    const int warp_m0 = (warp >> 1) * 32;   // 0,32,64,96
    const int warp_n0 = (warp & 1) * 32;    // 0,32
    const int bm = blockIdx.y * 128;
    const int bn = blockIdx.x * 64;

    float acc[2][4][4];
    #pragma unroll
    for (int t = 0; t < 2; t++)
        #pragma unroll
        for (int u = 0; u < 4; u++)
            #pragma unroll
            for (int r = 0; r < 4; r++) acc[t][u][r] = 0.f;

    // register staging for the in-flight chunk
    float4 ra[4];
    float  rb0[4], rb1[4];

    // ---- issue global loads for chunk at k0 (results land in regs) ----
    auto ldg_chunk = [&](int k0) {
        #pragma unroll
        for (int i = 0; i < 4; i++) {          // A: 128 rows x 32 k = 1024 f4
            const int idx = tid + i * 256;
            const int row = idx >> 3;
            const int c4  = (idx & 7) * 4;
            ra[i] = *(const float4*)(A + (size_t)(bm + row) * K + k0 + c4);
        }
        #pragma unroll
        for (int i = 0; i < 4; i++) {          // B: 64 n x 16 k-pairs
            const int idx = tid + i * 256;
            const int n  = idx & 63;
            const int kp = idx >> 6;
            const float* wp = W + (size_t)(k0 + 2 * kp) * N + bn + n;
            rb0[i] = __ldg(wp);
            rb1[i] = __ldg(wp + N);
        }
    };

    // ---- split staged regs to bf16 hi/lo and store into stage `buf` ----
    auto sts_chunk = [&](int buf) {
        __nv_bfloat16* Ah = sm + buf * STAGE_E;
        __nv_bfloat16* Al = Ah + A_TILE_E;
        __nv_bfloat16* Bh = Al + A_TILE_E;
        __nv_bfloat16* Bl = Bh + B_TILE_E;
        #pragma unroll
        for (int i = 0; i < 4; i++) {
            const int idx = tid + i * 256;
            const int row = idx >> 3;
            const int c4  = (idx & 7) * 4;
            uint32_t h0, l0, h1, l1;
            split2(ra[i].x, ra[i].y, h0, l0);
            split2(ra[i].z, ra[i].w, h1, l1);
            *(uint2*)(Ah + row * PITCH + c4) = make_uint2(h0, h1);
            *(uint2*)(Al + row * PITCH + c4) = make_uint2(l0, l1);
        }
        #pragma unroll
        for (int i = 0; i < 4; i++) {
            const int idx = tid + i * 256;
            const int n  = idx & 63;
            const int kp = idx >> 6;
            uint32_t hp, lp;
            split2(rb0[i], rb1[i], hp, lp);
            *(uint32_t*)(Bh + n * PITCH + 2 * kp) = hp;
            *(uint32_t*)(Bl + n * PITCH + 2 * kp) = lp;
        }
    };

    // ---- compute one K-chunk from stage `buf` ----
    auto compute_stage = [&](int buf) {
        const __nv_bfloat16* Ah = sm + buf * STAGE_E;
        const __nv_bfloat16* Al = Ah + A_TILE_E;
        const __nv_bfloat16* Bh = Al + A_TILE_E;
        const __nv_bfloat16* Bl = Bh + B_TILE_E;

        #pragma unroll
        for (int ks = 0; ks < KC; ks += 16) {
            uint32_t af[2][4], bh[4][2], bl[4][2];
            #pragma unroll
            for (int t = 0; t < 2; t++) {
                const __nv_bfloat16* p = Ah + (warp_m0 + t * 16 + g) * PITCH + ks + tig * 2;
                af[t][0] = *(const uint32_t*)p;
                af[t][1] = *(const uint32_t*)(p + 8 * PITCH);
                af[t][2] = *(const uint32_t*)(p + 8);
                af[t][3] = *(const uint32_t*)(p + 8 * PITCH + 8);
            }
            #pragma unroll
            for (int u = 0; u < 4; u++) {
                const __nv_bfloat16* p = Bh + (warp_n0 + u * 8 + g) * PITCH + ks + tig * 2;
                bh[u][0] = *(const uint32_t*)p;
                bh[u][1] = *(const uint32_t*)(p + 8);
                const __nv_bfloat16* q = Bl + (warp_n0 + u * 8 + g) * PITCH + ks + tig * 2;
                bl[u][0] = *(const uint32_t*)q;
                bl[u][1] = *(const uint32_t*)(q + 8);
            }
            // pass 1: hi*hi (8 independent accumulators)
            #pragma unroll
            for (int t = 0; t < 2; t++)
                #pragma unroll
                for (int u = 0; u < 4; u++)
                    MMA16816(acc[t][u], af[t], bh[u]);
            // pass 2: hi*lo
            #pragma unroll
            for (int t = 0; t < 2; t++)
                #pragma unroll
                for (int u = 0; u < 4; u++)
                    MMA16816(acc[t][u], af[t], bl[u]);
            // pass 3: lo*hi (reload A frags with lo)
            #pragma unroll
            for (int t = 0; t < 2; t++) {
                const __nv_bfloat16* p = Al + (warp_m0 + t * 16 + g) * PITCH + ks + tig * 2;
                af[t][0] = *(const uint32_t*)p;
                af[t][1] = *(const uint32_t*)(p + 8 * PITCH);
                af[t][2] = *(const uint32_t*)(p + 8);
                af[t][3] = *(const uint32_t*)(p + 8 * PITCH + 8);
            }
            #pragma unroll
            for (int t = 0; t < 2; t++)
                #pragma unroll
                for (int u = 0; u < 4; u++)
                    MMA16816(acc[t][u], af[t], bh[u]);
        }
    };

    const int NC = K / KC;   // 32
    ldg_chunk(0);
    sts_chunk(0);
    __syncthreads();

    for (int c = 0; c < NC; c++) {
        if (c + 1 < NC) ldg_chunk((c + 1) * KC);   // LDG in flight during compute
        compute_stage(c & 1);
        if (c + 1 < NC) sts_chunk((c + 1) & 1);    // consume LDG after compute
        __syncthreads();
    }

    // ---- epilogue: bias + store ----
    #pragma unroll
    for (int t = 0; t < 2; t++) {
        const int r0 = bm + warp_m0 + t * 16 + g;
        #pragma unroll
        for (int u = 0; u < 4; u++) {
            const int cb = bn + warp_n0 + u * 8 + tig * 2;
            const float2 bv = *(const float2*)(bias + cb);
            *(float2*)(C + (size_t)r0 * N + cb) =
                make_float2(acc[t][u][0] + bv.x, acc[t][u][1] + bv.y);
            *(float2*)(C + (size_t)(r0 + 8) * N + cb) =
                make_float2(acc[t][u][2] + bv.x, acc[t][u][3] + bv.y);
        }
    }
}

// ---------------------------------------------------------------------------
// Flash attention, fp32, online softmax (proven R8 baseline, fp32 heads out).
// ---------------------------------------------------------------------------
__global__ __launch_bounds__(256, 2)
void flash_kernel(const float* __restrict__ q, const float* __restrict__ kv,
                  float* __restrict__ heads)
{
    __shared__ float Qt[64][68];
    __shared__ float Kt[64][36];
    __shared__ float Vs[32][64];
    __shared__ float Ps[64][33];

    const int bh  = blockIdx.y;
    const int b   = bh >> 4;
    const int h   = bh & 15;
    const int q0  = blockIdx.x * 64;
    const int tid = threadIdx.x;
    const int tx  = tid & 15;
    const int ty  = tid >> 4;

    const float* qb = q  + (size_t)(b * Ss + q0) * Dm + h * HD;
    const float* kb = kv + (size_t)b * Ss * (2 * Dm) + h * HD;
    const float* vb = kb + Dm;

    for (int v = tid; v < 1024; v += 256) {
        const int r = v >> 4;
        const int c = (v & 15) * 4;
        const float4 t = *(const float4*)(qb + (size_t)r * Dm + c);
        Qt[c + 0][r] = t.x; Qt[c + 1][r] = t.y;
        Qt[c + 2][r] = t.z; Qt[c + 3][r] = t.w;
    }

    float m[4], l[4], o[4][4];
    #pragma unroll
    for (int i = 0; i < 4; i++) {
        m[i] = -1e30f; l[i] = 0.f;
        #pragma unroll
        for (int j = 0; j < 4; j++) o[i][j] = 0.f;
    }

    const int kr = tid >> 4;
    const int kc = (tid & 15) * 4;

    for (int kt = 0; kt < Ss; kt += 32) {
        __syncthreads();

        const float4 k0v = *(const float4*)(kb + (size_t)(kt + kr)      * (2 * Dm) + kc);
        const float4 k1v = *(const float4*)(kb + (size_t)(kt + kr + 16) * (2 * Dm) + kc);
        const float4 v0v = *(const float4*)(vb + (size_t)(kt + kr)      * (2 * Dm) + kc);
        const float4 v1v = *(const float4*)(vb + (size_t)(kt + kr + 16) * (2 * Dm) + kc);
        Kt[kc + 0][kr] = k0v.x; Kt[kc + 1][kr] = k0v.y;
        Kt[kc + 2][kr] = k0v.z; Kt[kc + 3][kr] = k0v.w;
        Kt[kc + 0][kr + 16] = k1v.x; Kt[kc + 1][kr + 16] = k1v.y;
        Kt[kc + 2][kr + 16] = k1v.z; Kt[kc + 3][kr + 16] = k1v.w;
        *(float4*)&Vs[kr][kc]      = v0v;
        *(float4*)&Vs[kr + 16][kc] = v1v;
        __syncthreads();

        float s0[4] = {0.f, 0.f, 0.f, 0.f};
        float s1[4] = {0.f, 0.f, 0.f, 0.f};
        #pragma unroll 16
        for (int d = 0; d < 64; d++) {
            const float4 a  = *(const float4*)&Qt[d][ty * 4];
            const float2 bk = *(const float2*)&Kt[d][tx * 2];
            s0[0] = fmaf(a.x, bk.x, s0[0]); s1[0] = fmaf(a.x, bk.y, s1[0]);
            s0[1] = fmaf(a.y, bk.x, s0[1]); s1[1] = fmaf(a.y, bk.y, s1[1]);
            s0[2] = fmaf(a.z, bk.x, s0[2]); s1[2] = fmaf(a.z, bk.y, s1[2]);
            s0[3] = fmaf(a.w, bk.x, s0[3]); s1[3] = fmaf(a.w, bk.y, s1[3]);
        }

        float rm[4];
        #pragma unroll
        for (int i = 0; i < 4; i++) {
            s0[i] *= 0.125f; s1[i] *= 0.125f;
            rm[i] = fmaxf(s0[i], s1[i]);
        }
        #pragma unroll
        for (int off = 8; off; off >>= 1) {
            #pragma unroll
            for (int i = 0; i < 4; i++)
                rm[i] = fmaxf(rm[i], __shfl_xor_sync(0xffffffffu, rm[i], off, 16));
        }

        float rs[4];
        #pragma unroll
        for (int i = 0; i < 4; i++) {
            const float mn    = fmaxf(m[i], rm[i]);
            const float alpha = __expf(m[i] - mn);
            m[i] = mn;
            const float p0 = __expf(s0[i] - mn);
            const float p1 = __expf(s1[i] - mn);
            Ps[ty * 4 + i][tx * 2 + 0] = p0;
            Ps[ty * 4 + i][tx * 2 + 1] = p1;
            rs[i] = p0 + p1;
            l[i] *= alpha;
            o[i][0] *= alpha; o[i][1] *= alpha; o[i][2] *= alpha; o[i][3] *= alpha;
        }
        #pragma unroll
        for (int off = 8; off; off >>= 1) {
            #pragma unroll
            for (int i = 0; i < 4; i++)
                rs[i] += __shfl_xor_sync(0xffffffffu, rs[i], off, 16);
        }
        #pragma unroll
        for (int i = 0; i < 4; i++) l[i] += rs[i];

        __syncthreads();

        #pragma unroll 8
        for (int k2 = 0; k2 < 32; k2++) {
            const float4 vv = *(const float4*)&Vs[k2][tx * 4];
            const float p0 = Ps[ty * 4 + 0][k2];
            const float p1 = Ps[ty * 4 + 1][k2];
            const float p2 = Ps[ty * 4 + 2][k2];
            const float p3 = Ps[ty * 4 + 3][k2];
            o[0][0] = fmaf(p0, vv.x, o[0][0]); o[0][1] = fmaf(p0, vv.y, o[0][1]);
            o[0][2] = fmaf(p0, vv.z, o[0][2]); o[0][3] = fmaf(p0, vv.w, o[0][3]);
            o[1][0] = fmaf(p1, vv.x, o[1][0]); o[1][1] = fmaf(p1, vv.y, o[1][1]);
            o[1][2] = fmaf(p1, vv.z, o[1][2]); o[1][3] = fmaf(p1, vv.w, o[1][3]);
            o[2][0] = fmaf(p2, vv.x, o[2][0]); o[2][1] = fmaf(p2, vv.y, o[2][1]);
            o[2][2] = fmaf(p2, vv.z, o[2][2]); o[2][3] = fmaf(p2, vv.w, o[2][3]);
            o[3][0] = fmaf(p3, vv.x, o[3][0]); o[3][1] = fmaf(p3, vv.y, o[3][1]);
            o[3][2] = fmaf(p3, vv.z, o[3][2]); o[3][3] = fmaf(p3, vv.w, o[3][3]);
        }
    }

    #pragma unroll
    for (int i = 0; i < 4; i++) {
        const float inv = 1.f / l[i];
        const float4 r = make_float4(o[i][0] * inv, o[i][1] * inv,
                                     o[i][2] * inv, o[i][3] * inv);
        *(float4*)(heads + (size_t)(b * Ss + q0 + ty * 4 + i) * Dm + h * HD + tx * 4) = r;
    }
}

// ---------------------------------------------------------------------------
// Launch
// ---------------------------------------------------------------------------
extern "C" void kernel_launch(void* const* d_in, const int* in_sizes, int n_in,
                              void* d_out, int out_size)
{
    const float* query = (const float*)d_in[0];
    const float* value = (const float*)d_in[1];
    const float* Wq    = (const float*)d_in[2];
    const float* bq    = (const float*)d_in[3];
    const float* Wkv   = (const float*)d_in[4];
    const float* bkv   = (const float*)d_in[5];
    const float* Wo    = (const float*)d_in[6];
    const float* bo    = (const float*)d_in[7];
    float* out = (float*)d_out;

    float *qbuf, *kvbuf, *hbuf;
    cudaGetSymbolAddress((void**)&qbuf,  g_q);
    cudaGetSymbolAddress((void**)&kvbuf, g_kv);
    cudaGetSymbolAddress((void**)&hbuf,  g_heads);

    cudaFuncSetAttribute(gemm_mma_kernel,
                         cudaFuncAttributeMaxDynamicSharedMemorySize, GEMM_SMEM);

    // 1) q = query @ Wq + bq        [8192,1024]
    gemm_mma_kernel<<<dim3(Dm / 64, M_ROWS / 128), 256, GEMM_SMEM>>>(
        query, Wq, bq, qbuf, Dm, Dm);

    // 2) kv = value @ Wkv + bkv     [8192,2048]
    gemm_mma_kernel<<<dim3(2 * Dm / 64, M_ROWS / 128), 256, GEMM_SMEM>>>(
        value, Wkv, bkv, kvbuf, 2 * Dm, Dm);

    // 3) heads = softmax(q k^T / sqrt(HD)) v   (per head, flash)
    flash_kernel<<<dim3(Ss / 64, Bb * Hn), 256>>>(qbuf, kvbuf, hbuf);

    // 4) out = heads @ Wo + bo      [8192,1024]
    gemm_mma_kernel<<<dim3(Dm / 64, M_ROWS / 128), 256, GEMM_SMEM>>>(
        hbuf, Wo, bo, out, Dm, Dm);
}

// round 13
// speedup vs baseline: 1.4147x; 1.4147x over previous
#include <cuda_runtime.h>
#include <cuda_bf16.h>
#include <cstdint>

// Problem constants
#define Dm 1024
#define Hn 16
#define HD 64
#define Bb 8
#define Ss 1024
#define M_ROWS (Bb * Ss)          // 8192

// Scratch (no runtime allocation allowed)
__device__ float g_q[(size_t)M_ROWS * Dm];        // 33.5 MB
__device__ float g_kv[(size_t)M_ROWS * 2 * Dm];   // 67 MB
__device__ float g_heads[(size_t)M_ROWS * Dm];    // 33.5 MB

// ===========================================================================
// Helpers
// ===========================================================================
#define MMA16816(c, a, b)                                                     \
    asm volatile("mma.sync.aligned.m16n8k16.row.col.f32.bf16.bf16.f32 "       \
        "{%0,%1,%2,%3}, {%4,%5,%6,%7}, {%8,%9}, {%0,%1,%2,%3};"               \
        : "+f"((c)[0]), "+f"((c)[1]), "+f"((c)[2]), "+f"((c)[3])              \
        : "r"((a)[0]), "r"((a)[1]), "r"((a)[2]), "r"((a)[3]),                 \
          "r"((b)[0]), "r"((b)[1]))

// fp32 pair -> (hi bf16 pair, lo bf16 pair) packed as uint32
__device__ __forceinline__ void split2(float x, float y, uint32_t& hi, uint32_t& lo) {
    __nv_bfloat16 hx = __float2bfloat16(x), hy = __float2bfloat16(y);
    __nv_bfloat16 lx = __float2bfloat16(x - __bfloat162float(hx));
    __nv_bfloat16 ly = __float2bfloat16(y - __bfloat162float(hy));
    hi = (uint32_t)__bfloat16_as_ushort(hx) | ((uint32_t)__bfloat16_as_ushort(hy) << 16);
    lo = (uint32_t)__bfloat16_as_ushort(lx) | ((uint32_t)__bfloat16_as_ushort(ly) << 16);
}

// ===========================================================================
// HMMA GEMM + bias, bf16x3 split (fp32-accurate): C[M,N] = A[M,K]@W[K,N]+bias
// CTA tile 128x128 (R8's arithmetic intensity), 512 threads / 16 warps
// (R12's 4 warps/SMSP latency hiding), warp grid 4x4, warp tile 32x32.
//  - acc = 32 regs/thread -> ~90 regs total, no spills, no bounds cap.
//  - Plain LDG->split->STS loader issued before compute of the current
//    chunk; 4 warps/SMSP cover the latency.
// Smem pitch 36 elems (72 B): conflict-light for the m16n8k16 thread map.
// ===========================================================================
#define KC 32
#define PITCH 36
#define T_E (128 * PITCH)                      // one 128x32 tile: 4608 bf16
#define STAGE_E (4 * T_E)                      // Ahi,Alo,Bhi,Blo = 18432
#define STAGE_B (STAGE_E * 2)                  // 36864 B
#define GEMM_SMEM (2 * STAGE_B)                // 73728 B
#define NTHR 512

__global__ __launch_bounds__(NTHR)
void gemm_mma_kernel(const float* __restrict__ A, const float* __restrict__ W,
                     const float* __restrict__ bias, float* __restrict__ C,
                     int N, int K)
{
    extern __shared__ __nv_bfloat16 sm[];

    const int tid  = threadIdx.x;
    const int lane = tid & 31;
    const int warp = tid >> 5;         // 0..15
    const int g    = lane >> 2;        // row within 8-row block
    const int tig  = lane & 3;         // thread in group
    const int warp_m0 = (warp >> 2) * 32;   // 0,32,64,96
    const int warp_n0 = (warp & 3) * 32;    // 0,32,64,96
    const int bm = blockIdx.y * 128;
    const int bn = blockIdx.x * 128;

    float acc[2][4][4];
    #pragma unroll
    for (int t = 0; t < 2; t++)
        #pragma unroll
        for (int u = 0; u < 4; u++)
            #pragma unroll
            for (int r = 0; r < 4; r++) acc[t][u][r] = 0.f;

    // ---- chunk loader: global fp32 -> split bf16 smem tiles ----
    auto load_chunk = [&](int buf, int k0) {
        __nv_bfloat16* Ah = sm + buf * STAGE_E;
        __nv_bfloat16* Al = Ah + T_E;
        __nv_bfloat16* Bh = Al + T_E;
        __nv_bfloat16* Bl = Bh + T_E;

        // A: 128 rows x 32 k fp32 = 1024 float4 / 512 thr = 2 each
        #pragma unroll
        for (int i = 0; i < 2; i++) {
            const int idx = tid + i * NTHR;
            const int row = idx >> 3;
            const int c4  = (idx & 7) * 4;
            const float4 a = *(const float4*)(A + (size_t)(bm + row) * K + k0 + c4);
            uint32_t h0, l0, h1, l1;
            split2(a.x, a.y, h0, l0);
            split2(a.z, a.w, h1, l1);
            *(uint2*)(Ah + row * PITCH + c4) = make_uint2(h0, h1);
            *(uint2*)(Al + row * PITCH + c4) = make_uint2(l0, l1);
        }

        // B: Bs[n][k] = W[k0+k][bn+n]; 128 n x 16 k-pairs = 2048 / 512 = 4 each
        #pragma unroll
        for (int i = 0; i < 4; i++) {
            const int idx = tid + i * NTHR;
            const int n  = idx & 127;        // coalesced across lanes
            const int kp = idx >> 7;
            const float* wp = W + (size_t)(k0 + 2 * kp) * N + bn + n;
            const float w0 = __ldg(wp);
            const float w1 = __ldg(wp + N);
            uint32_t hp, lp;
            split2(w0, w1, hp, lp);
            *(uint32_t*)(Bh + n * PITCH + 2 * kp) = hp;
            *(uint32_t*)(Bl + n * PITCH + 2 * kp) = lp;
        }
    };

    // ---- compute one K-chunk from stage `buf` ----
    auto compute_stage = [&](int buf) {
        const __nv_bfloat16* Ah = sm + buf * STAGE_E;
        const __nv_bfloat16* Al = Ah + T_E;
        const __nv_bfloat16* Bh = Al + T_E;
        const __nv_bfloat16* Bl = Bh + T_E;

        #pragma unroll
        for (int ks = 0; ks < KC; ks += 16) {
            uint32_t af[2][4], bh[4][2], bl[4][2];
            #pragma unroll
            for (int t = 0; t < 2; t++) {
                const __nv_bfloat16* p = Ah + (warp_m0 + t * 16 + g) * PITCH + ks + tig * 2;
                af[t][0] = *(const uint32_t*)p;
                af[t][1] = *(const uint32_t*)(p + 8 * PITCH);
                af[t][2] = *(const uint32_t*)(p + 8);
                af[t][3] = *(const uint32_t*)(p + 8 * PITCH + 8);
            }
            #pragma unroll
            for (int u = 0; u < 4; u++) {
                const __nv_bfloat16* p = Bh + (warp_n0 + u * 8 + g) * PITCH + ks + tig * 2;
                bh[u][0] = *(const uint32_t*)p;
                bh[u][1] = *(const uint32_t*)(p + 8);
                const __nv_bfloat16* q = Bl + (warp_n0 + u * 8 + g) * PITCH + ks + tig * 2;
                bl[u][0] = *(const uint32_t*)q;
                bl[u][1] = *(const uint32_t*)(q + 8);
            }
            // pass 1: hi*hi (8 independent accumulators before reuse)
            #pragma unroll
            for (int t = 0; t < 2; t++)
                #pragma unroll
                for (int u = 0; u < 4; u++)
                    MMA16816(acc[t][u], af[t], bh[u]);
            // pass 2: hi*lo
            #pragma unroll
            for (int t = 0; t < 2; t++)
                #pragma unroll
                for (int u = 0; u < 4; u++)
                    MMA16816(acc[t][u], af[t], bl[u]);
            // pass 3: lo*hi (reload A frags with lo)
            #pragma unroll
            for (int t = 0; t < 2; t++) {
                const __nv_bfloat16* p = Al + (warp_m0 + t * 16 + g) * PITCH + ks + tig * 2;
                af[t][0] = *(const uint32_t*)p;
                af[t][1] = *(const uint32_t*)(p + 8 * PITCH);
                af[t][2] = *(const uint32_t*)(p + 8);
                af[t][3] = *(const uint32_t*)(p + 8 * PITCH + 8);
            }
            #pragma unroll
            for (int t = 0; t < 2; t++)
                #pragma unroll
                for (int u = 0; u < 4; u++)
                    MMA16816(acc[t][u], af[t], bh[u]);
        }
    };

    const int NC = K / KC;   // 32
    load_chunk(0, 0);
    __syncthreads();
    for (int c = 0; c < NC; c++) {
        if (c + 1 < NC) load_chunk((c + 1) & 1, (c + 1) * KC);
        compute_stage(c & 1);
        __syncthreads();
    }

    // ---- epilogue: bias + store ----
    #pragma unroll
    for (int t = 0; t < 2; t++) {
        const int r0 = bm + warp_m0 + t * 16 + g;
        #pragma unroll
        for (int u = 0; u < 4; u++) {
            const int cb = bn + warp_n0 + u * 8 + tig * 2;
            const float2 bv = *(const float2*)(bias + cb);
            *(float2*)(C + (size_t)r0 * N + cb) =
                make_float2(acc[t][u][0] + bv.x, acc[t][u][1] + bv.y);
            *(float2*)(C + (size_t)(r0 + 8) * N + cb) =
                make_float2(acc[t][u][2] + bv.x, acc[t][u][3] + bv.y);
        }
    }
}

// ---------------------------------------------------------------------------
// Flash attention, fp32, online softmax (proven baseline).
// ---------------------------------------------------------------------------
__global__ __launch_bounds__(256, 2)
void flash_kernel(const float* __restrict__ q, const float* __restrict__ kv,
                  float* __restrict__ heads)
{
    __shared__ float Qt[64][68];
    __shared__ float Kt[64][36];
    __shared__ float Vs[32][64];
    __shared__ float Ps[64][33];

    const int bh  = blockIdx.y;
    const int b   = bh >> 4;
    const int h   = bh & 15;
    const int q0  = blockIdx.x * 64;
    const int tid = threadIdx.x;
    const int tx  = tid & 15;
    const int ty  = tid >> 4;

    const float* qb = q  + (size_t)(b * Ss + q0) * Dm + h * HD;
    const float* kb = kv + (size_t)b * Ss * (2 * Dm) + h * HD;
    const float* vb = kb + Dm;

    for (int v = tid; v < 1024; v += 256) {
        const int r = v >> 4;
        const int c = (v & 15) * 4;
        const float4 t = *(const float4*)(qb + (size_t)r * Dm + c);
        Qt[c + 0][r] = t.x; Qt[c + 1][r] = t.y;
        Qt[c + 2][r] = t.z; Qt[c + 3][r] = t.w;
    }

    float m[4], l[4], o[4][4];
    #pragma unroll
    for (int i = 0; i < 4; i++) {
        m[i] = -1e30f; l[i] = 0.f;
        #pragma unroll
        for (int j = 0; j < 4; j++) o[i][j] = 0.f;
    }

    const int kr = tid >> 4;
    const int kc = (tid & 15) * 4;

    for (int kt = 0; kt < Ss; kt += 32) {
        __syncthreads();

        const float4 k0v = *(const float4*)(kb + (size_t)(kt + kr)      * (2 * Dm) + kc);
        const float4 k1v = *(const float4*)(kb + (size_t)(kt + kr + 16) * (2 * Dm) + kc);
        const float4 v0v = *(const float4*)(vb + (size_t)(kt + kr)      * (2 * Dm) + kc);
        const float4 v1v = *(const float4*)(vb + (size_t)(kt + kr + 16) * (2 * Dm) + kc);
        Kt[kc + 0][kr] = k0v.x; Kt[kc + 1][kr] = k0v.y;
        Kt[kc + 2][kr] = k0v.z; Kt[kc + 3][kr] = k0v.w;
        Kt[kc + 0][kr + 16] = k1v.x; Kt[kc + 1][kr + 16] = k1v.y;
        Kt[kc + 2][kr + 16] = k1v.z; Kt[kc + 3][kr + 16] = k1v.w;
        *(float4*)&Vs[kr][kc]      = v0v;
        *(float4*)&Vs[kr + 16][kc] = v1v;
        __syncthreads();

        float s0[4] = {0.f, 0.f, 0.f, 0.f};
        float s1[4] = {0.f, 0.f, 0.f, 0.f};
        #pragma unroll 16
        for (int d = 0; d < 64; d++) {
            const float4 a  = *(const float4*)&Qt[d][ty * 4];
            const float2 bk = *(const float2*)&Kt[d][tx * 2];
            s0[0] = fmaf(a.x, bk.x, s0[0]); s1[0] = fmaf(a.x, bk.y, s1[0]);
            s0[1] = fmaf(a.y, bk.x, s0[1]); s1[1] = fmaf(a.y, bk.y, s1[1]);
            s0[2] = fmaf(a.z, bk.x, s0[2]); s1[2] = fmaf(a.z, bk.y, s1[2]);
            s0[3] = fmaf(a.w, bk.x, s0[3]); s1[3] = fmaf(a.w, bk.y, s1[3]);
        }

        float rm[4];
        #pragma unroll
        for (int i = 0; i < 4; i++) {
            s0[i] *= 0.125f; s1[i] *= 0.125f;
            rm[i] = fmaxf(s0[i], s1[i]);
        }
        #pragma unroll
        for (int off = 8; off; off >>= 1) {
            #pragma unroll
            for (int i = 0; i < 4; i++)
                rm[i] = fmaxf(rm[i], __shfl_xor_sync(0xffffffffu, rm[i], off, 16));
        }

        float rs[4];
        #pragma unroll
        for (int i = 0; i < 4; i++) {
            const float mn    = fmaxf(m[i], rm[i]);
            const float alpha = __expf(m[i] - mn);
            m[i] = mn;
            const float p0 = __expf(s0[i] - mn);
            const float p1 = __expf(s1[i] - mn);
            Ps[ty * 4 + i][tx * 2 + 0] = p0;
            Ps[ty * 4 + i][tx * 2 + 1] = p1;
            rs[i] = p0 + p1;
            l[i] *= alpha;
            o[i][0] *= alpha; o[i][1] *= alpha; o[i][2] *= alpha; o[i][3] *= alpha;
        }
        #pragma unroll
        for (int off = 8; off; off >>= 1) {
            #pragma unroll
            for (int i = 0; i < 4; i++)
                rs[i] += __shfl_xor_sync(0xffffffffu, rs[i], off, 16);
        }
        #pragma unroll
        for (int i = 0; i < 4; i++) l[i] += rs[i];

        __syncthreads();

        #pragma unroll 8
        for (int k2 = 0; k2 < 32; k2++) {
            const float4 vv = *(const float4*)&Vs[k2][tx * 4];
            const float p0 = Ps[ty * 4 + 0][k2];
            const float p1 = Ps[ty * 4 + 1][k2];
            const float p2 = Ps[ty * 4 + 2][k2];
            const float p3 = Ps[ty * 4 + 3][k2];
            o[0][0] = fmaf(p0, vv.x, o[0][0]); o[0][1] = fmaf(p0, vv.y, o[0][1]);
            o[0][2] = fmaf(p0, vv.z, o[0][2]); o[0][3] = fmaf(p0, vv.w, o[0][3]);
            o[1][0] = fmaf(p1, vv.x, o[1][0]); o[1][1] = fmaf(p1, vv.y, o[1][1]);
            o[1][2] = fmaf(p1, vv.z, o[1][2]); o[1][3] = fmaf(p1, vv.w, o[1][3]);
            o[2][0] = fmaf(p2, vv.x, o[2][0]); o[2][1] = fmaf(p2, vv.y, o[2][1]);
            o[2][2] = fmaf(p2, vv.z, o[2][2]); o[2][3] = fmaf(p2, vv.w, o[2][3]);
            o[3][0] = fmaf(p3, vv.x, o[3][0]); o[3][1] = fmaf(p3, vv.y, o[3][1]);
            o[3][2] = fmaf(p3, vv.z, o[3][2]); o[3][3] = fmaf(p3, vv.w, o[3][3]);
        }
    }

    #pragma unroll
    for (int i = 0; i < 4; i++) {
        const float inv = 1.f / l[i];
        const float4 r = make_float4(o[i][0] * inv, o[i][1] * inv,
                                     o[i][2] * inv, o[i][3] * inv);
        *(float4*)(heads + (size_t)(b * Ss + q0 + ty * 4 + i) * Dm + h * HD + tx * 4) = r;
    }
}

// ---------------------------------------------------------------------------
// Launch
// ---------------------------------------------------------------------------
extern "C" void kernel_launch(void* const* d_in, const int* in_sizes, int n_in,
                              void* d_out, int out_size)
{
    const float* query = (const float*)d_in[0];
    const float* value = (const float*)d_in[1];
    const float* Wq    = (const float*)d_in[2];
    const float* bq    = (const float*)d_in[3];
    const float* Wkv   = (const float*)d_in[4];
    const float* bkv   = (const float*)d_in[5];
    const float* Wo    = (const float*)d_in[6];
    const float* bo    = (const float*)d_in[7];
    float* out = (float*)d_out;

    float *qbuf, *kvbuf, *hbuf;
    cudaGetSymbolAddress((void**)&qbuf,  g_q);
    cudaGetSymbolAddress((void**)&kvbuf, g_kv);
    cudaGetSymbolAddress((void**)&hbuf,  g_heads);

    cudaFuncSetAttribute(gemm_mma_kernel,
                         cudaFuncAttributeMaxDynamicSharedMemorySize, GEMM_SMEM);

    // 1) q = query @ Wq + bq        [8192,1024]
    gemm_mma_kernel<<<dim3(Dm / 128, M_ROWS / 128), NTHR, GEMM_SMEM>>>(
        query, Wq, bq, qbuf, Dm, Dm);

    // 2) kv = value @ Wkv + bkv     [8192,2048]
    gemm_mma_kernel<<<dim3(2 * Dm / 128, M_ROWS / 128), NTHR, GEMM_SMEM>>>(
        value, Wkv, bkv, kvbuf, 2 * Dm, Dm);

    // 3) heads = softmax(q k^T / sqrt(HD)) v   (per head, flash)
    flash_kernel<<<dim3(Ss / 64, Bb * Hn), 256>>>(qbuf, kvbuf, hbuf);

    // 4) out = heads @ Wo + bo      [8192,1024]
    gemm_mma_kernel<<<dim3(Dm / 128, M_ROWS / 128), NTHR, GEMM_SMEM>>>(
        hbuf, Wo, bo, out, Dm, Dm);
}

// round 15
// speedup vs baseline: 1.5529x; 1.0977x over previous
#include <cuda_runtime.h>
#include <cuda_bf16.h>
#include <cstdint>

// Problem constants
#define Dm 1024
#define Hn 16
#define HD 64
#define Bb 8
#define Ss 1024
#define M_ROWS (Bb * Ss)          // 8192

// Scratch (no runtime allocation allowed)
__device__ float g_q[(size_t)M_ROWS * Dm];        // 33.5 MB
__device__ float g_kv[(size_t)M_ROWS * 2 * Dm];   // 67 MB
__device__ float g_heads[(size_t)M_ROWS * Dm];    // 33.5 MB

// ===========================================================================
// Helpers
// ===========================================================================
#define MMA16816(c, a, b)                                                     \
    asm volatile("mma.sync.aligned.m16n8k16.row.col.f32.bf16.bf16.f32 "       \
        "{%0,%1,%2,%3}, {%4,%5,%6,%7}, {%8,%9}, {%0,%1,%2,%3};"               \
        : "+f"((c)[0]), "+f"((c)[1]), "+f"((c)[2]), "+f"((c)[3])              \
        : "r"((a)[0]), "r"((a)[1]), "r"((a)[2]), "r"((a)[3]),                 \
          "r"((b)[0]), "r"((b)[1]))

// fp32 pair -> (hi bf16 pair, lo bf16 pair) packed as uint32
__device__ __forceinline__ void split2(float x, float y, uint32_t& hi, uint32_t& lo) {
    __nv_bfloat16 hx = __float2bfloat16(x), hy = __float2bfloat16(y);
    __nv_bfloat16 lx = __float2bfloat16(x - __bfloat162float(hx));
    __nv_bfloat16 ly = __float2bfloat16(y - __bfloat162float(hy));
    hi = (uint32_t)__bfloat16_as_ushort(hx) | ((uint32_t)__bfloat16_as_ushort(hy) << 16);
    lo = (uint32_t)__bfloat16_as_ushort(lx) | ((uint32_t)__bfloat16_as_ushort(ly) << 16);
}

// ===========================================================================
// HMMA GEMM + bias, bf16x3 split (fp32-accurate): C[M,N] = A[M,K]@W[K,N]+bias
// CTA tile 128x128, 512 threads / 16 warps (4x4 grid, warp tile 32x32).
// R14 change vs R13: loader split into ldg_chunk (global->regs, issued
// BEFORE compute of the current chunk) and sts_chunk (split+STS AFTER
// compute) -> the ~600cyc global latency is hidden under 48 MMAs instead
// of being serially exposed at each chunk boundary (R13: issue=24.1%).
// Staging regs: A 2xfloat4 + B 4x(2 floats) = 16 regs -> ~94 total, no spill.
// ===========================================================================
#define KC 32
#define PITCH 36
#define T_E (128 * PITCH)                      // one 128x32 tile: 4608 bf16
#define STAGE_E (4 * T_E)                      // Ahi,Alo,Bhi,Blo = 18432
#define STAGE_B (STAGE_E * 2)                  // 36864 B
#define GEMM_SMEM (2 * STAGE_B)                // 73728 B
#define NTHR 512

__global__ __launch_bounds__(NTHR)
void gemm_mma_kernel(const float* __restrict__ A, const float* __restrict__ W,
                     const float* __restrict__ bias, float* __restrict__ C,
                     int N, int K)
{
    extern __shared__ __nv_bfloat16 sm[];

    const int tid  = threadIdx.x;
    const int lane = tid & 31;
    const int warp = tid >> 5;         // 0..15
    const int g    = lane >> 2;        // row within 8-row block
    const int tig  = lane & 3;         // thread in group
    const int warp_m0 = (warp >> 2) * 32;   // 0,32,64,96
    const int warp_n0 = (warp & 3) * 32;    // 0,32,64,96
    const int bm = blockIdx.y * 128;
    const int bn = blockIdx.x * 128;

    float acc[2][4][4];
    #pragma unroll
    for (int t = 0; t < 2; t++)
        #pragma unroll
        for (int u = 0; u < 4; u++)
            #pragma unroll
            for (int r = 0; r < 4; r++) acc[t][u][r] = 0.f;

    // register staging for the in-flight chunk
    float4 ra[2];
    float2 rb[4];

    // ---- issue global loads for chunk at k0 (results land in regs) ----
    auto ldg_chunk = [&](int k0) {
        // A: 128 rows x 32 k fp32 = 1024 float4 / 512 thr = 2 each
        #pragma unroll
        for (int i = 0; i < 2; i++) {
            const int idx = tid + i * NTHR;
            const int row = idx >> 3;
            const int c4  = (idx & 7) * 4;
            ra[i] = *(const float4*)(A + (size_t)(bm + row) * K + k0 + c4);
        }
        // B: 128 n x 16 k-pairs = 2048 items / 512 thr = 4 each
        #pragma unroll
        for (int i = 0; i < 4; i++) {
            const int idx = tid + i * NTHR;
            const int n  = idx & 127;        // coalesced across lanes
            const int kp = idx >> 7;
            const float* wp = W + (size_t)(k0 + 2 * kp) * N + bn + n;
            rb[i].x = __ldg(wp);
            rb[i].y = __ldg(wp + N);
        }
    };

    // ---- split staged regs to bf16 hi/lo, store into stage `buf` ----
    auto sts_chunk = [&](int buf) {
        __nv_bfloat16* Ah = sm + buf * STAGE_E;
        __nv_bfloat16* Al = Ah + T_E;
        __nv_bfloat16* Bh = Al + T_E;
        __nv_bfloat16* Bl = Bh + T_E;
        #pragma unroll
        for (int i = 0; i < 2; i++) {
            const int idx = tid + i * NTHR;
            const int row = idx >> 3;
            const int c4  = (idx & 7) * 4;
            uint32_t h0, l0, h1, l1;
            split2(ra[i].x, ra[i].y, h0, l0);
            split2(ra[i].z, ra[i].w, h1, l1);
            *(uint2*)(Ah + row * PITCH + c4) = make_uint2(h0, h1);
            *(uint2*)(Al + row * PITCH + c4) = make_uint2(l0, l1);
        }
        #pragma unroll
        for (int i = 0; i < 4; i++) {
            const int idx = tid + i * NTHR;
            const int n  = idx & 127;
            const int kp = idx >> 7;
            uint32_t hp, lp;
            split2(rb[i].x, rb[i].y, hp, lp);
            *(uint32_t*)(Bh + n * PITCH + 2 * kp) = hp;
            *(uint32_t*)(Bl + n * PITCH + 2 * kp) = lp;
        }
    };

    // ---- compute one K-chunk from stage `buf` ----
    auto compute_stage = [&](int buf) {
        const __nv_bfloat16* Ah = sm + buf * STAGE_E;
        const __nv_bfloat16* Al = Ah + T_E;
        const __nv_bfloat16* Bh = Al + T_E;
        const __nv_bfloat16* Bl = Bh + T_E;

        #pragma unroll
        for (int ks = 0; ks < KC; ks += 16) {
            uint32_t af[2][4], bh[4][2], bl[4][2];
            #pragma unroll
            for (int t = 0; t < 2; t++) {
                const __nv_bfloat16* p = Ah + (warp_m0 + t * 16 + g) * PITCH + ks + tig * 2;
                af[t][0] = *(const uint32_t*)p;
                af[t][1] = *(const uint32_t*)(p + 8 * PITCH);
                af[t][2] = *(const uint32_t*)(p + 8);
                af[t][3] = *(const uint32_t*)(p + 8 * PITCH + 8);
            }
            #pragma unroll
            for (int u = 0; u < 4; u++) {
                const __nv_bfloat16* p = Bh + (warp_n0 + u * 8 + g) * PITCH + ks + tig * 2;
                bh[u][0] = *(const uint32_t*)p;
                bh[u][1] = *(const uint32_t*)(p + 8);
                const __nv_bfloat16* q = Bl + (warp_n0 + u * 8 + g) * PITCH + ks + tig * 2;
                bl[u][0] = *(const uint32_t*)q;
                bl[u][1] = *(const uint32_t*)(q + 8);
            }
            // pass 1: hi*hi (8 independent accumulators before reuse)
            #pragma unroll
            for (int t = 0; t < 2; t++)
                #pragma unroll
                for (int u = 0; u < 4; u++)
                    MMA16816(acc[t][u], af[t], bh[u]);
            // pass 2: hi*lo
            #pragma unroll
            for (int t = 0; t < 2; t++)
                #pragma unroll
                for (int u = 0; u < 4; u++)
                    MMA16816(acc[t][u], af[t], bl[u]);
            // pass 3: lo*hi (reload A frags with lo)
            #pragma unroll
            for (int t = 0; t < 2; t++) {
                const __nv_bfloat16* p = Al + (warp_m0 + t * 16 + g) * PITCH + ks + tig * 2;
                af[t][0] = *(const uint32_t*)p;
                af[t][1] = *(const uint32_t*)(p + 8 * PITCH);
                af[t][2] = *(const uint32_t*)(p + 8);
                af[t][3] = *(const uint32_t*)(p + 8 * PITCH + 8);
            }
            #pragma unroll
            for (int t = 0; t < 2; t++)
                #pragma unroll
                for (int u = 0; u < 4; u++)
                    MMA16816(acc[t][u], af[t], bh[u]);
        }
    };

    const int NC = K / KC;   // 32
    ldg_chunk(0);
    sts_chunk(0);
    __syncthreads();

    for (int c = 0; c < NC; c++) {
        if (c + 1 < NC) ldg_chunk((c + 1) * KC);   // LDG in flight during compute
        compute_stage(c & 1);
        if (c + 1 < NC) sts_chunk((c + 1) & 1);    // consume LDG after compute
        __syncthreads();
    }

    // ---- epilogue: bias + store ----
    #pragma unroll
    for (int t = 0; t < 2; t++) {
        const int r0 = bm + warp_m0 + t * 16 + g;
        #pragma unroll
        for (int u = 0; u < 4; u++) {
            const int cb = bn + warp_n0 + u * 8 + tig * 2;
            const float2 bv = *(const float2*)(bias + cb);
            *(float2*)(C + (size_t)r0 * N + cb) =
                make_float2(acc[t][u][0] + bv.x, acc[t][u][1] + bv.y);
            *(float2*)(C + (size_t)(r0 + 8) * N + cb) =
                make_float2(acc[t][u][2] + bv.x, acc[t][u][3] + bv.y);
        }
    }
}

// ---------------------------------------------------------------------------
// Flash attention, fp32, online softmax (proven baseline).
// ---------------------------------------------------------------------------
__global__ __launch_bounds__(256, 2)
void flash_kernel(const float* __restrict__ q, const float* __restrict__ kv,
                  float* __restrict__ heads)
{
    __shared__ float Qt[64][68];
    __shared__ float Kt[64][36];
    __shared__ float Vs[32][64];
    __shared__ float Ps[64][33];

    const int bh  = blockIdx.y;
    const int b   = bh >> 4;
    const int h   = bh & 15;
    const int q0  = blockIdx.x * 64;
    const int tid = threadIdx.x;
    const int tx  = tid & 15;
    const int ty  = tid >> 4;

    const float* qb = q  + (size_t)(b * Ss + q0) * Dm + h * HD;
    const float* kb = kv + (size_t)b * Ss * (2 * Dm) + h * HD;
    const float* vb = kb + Dm;

    for (int v = tid; v < 1024; v += 256) {
        const int r = v >> 4;
        const int c = (v & 15) * 4;
        const float4 t = *(const float4*)(qb + (size_t)r * Dm + c);
        Qt[c + 0][r] = t.x; Qt[c + 1][r] = t.y;
        Qt[c + 2][r] = t.z; Qt[c + 3][r] = t.w;
    }

    float m[4], l[4], o[4][4];
    #pragma unroll
    for (int i = 0; i < 4; i++) {
        m[i] = -1e30f; l[i] = 0.f;
        #pragma unroll
        for (int j = 0; j < 4; j++) o[i][j] = 0.f;
    }

    const int kr = tid >> 4;
    const int kc = (tid & 15) * 4;

    for (int kt = 0; kt < Ss; kt += 32) {
        __syncthreads();

        const float4 k0v = *(const float4*)(kb + (size_t)(kt + kr)      * (2 * Dm) + kc);
        const float4 k1v = *(const float4*)(kb + (size_t)(kt + kr + 16) * (2 * Dm) + kc);
        const float4 v0v = *(const float4*)(vb + (size_t)(kt + kr)      * (2 * Dm) + kc);
        const float4 v1v = *(const float4*)(vb + (size_t)(kt + kr + 16) * (2 * Dm) + kc);
        Kt[kc + 0][kr] = k0v.x; Kt[kc + 1][kr] = k0v.y;
        Kt[kc + 2][kr] = k0v.z; Kt[kc + 3][kr] = k0v.w;
        Kt[kc + 0][kr + 16] = k1v.x; Kt[kc + 1][kr + 16] = k1v.y;
        Kt[kc + 2][kr + 16] = k1v.z; Kt[kc + 3][kr + 16] = k1v.w;
        *(float4*)&Vs[kr][kc]      = v0v;
        *(float4*)&Vs[kr + 16][kc] = v1v;
        __syncthreads();

        float s0[4] = {0.f, 0.f, 0.f, 0.f};
        float s1[4] = {0.f, 0.f, 0.f, 0.f};
        #pragma unroll 16
        for (int d = 0; d < 64; d++) {
            const float4 a  = *(const float4*)&Qt[d][ty * 4];
            const float2 bk = *(const float2*)&Kt[d][tx * 2];
            s0[0] = fmaf(a.x, bk.x, s0[0]); s1[0] = fmaf(a.x, bk.y, s1[0]);
            s0[1] = fmaf(a.y, bk.x, s0[1]); s1[1] = fmaf(a.y, bk.y, s1[1]);
            s0[2] = fmaf(a.z, bk.x, s0[2]); s1[2] = fmaf(a.z, bk.y, s1[2]);
            s0[3] = fmaf(a.w, bk.x, s0[3]); s1[3] = fmaf(a.w, bk.y, s1[3]);
        }

        float rm[4];
        #pragma unroll
        for (int i = 0; i < 4; i++) {
            s0[i] *= 0.125f; s1[i] *= 0.125f;
            rm[i] = fmaxf(s0[i], s1[i]);
        }
        #pragma unroll
        for (int off = 8; off; off >>= 1) {
            #pragma unroll
            for (int i = 0; i < 4; i++)
                rm[i] = fmaxf(rm[i], __shfl_xor_sync(0xffffffffu, rm[i], off, 16));
        }

        float rs[4];
        #pragma unroll
        for (int i = 0; i < 4; i++) {
            const float mn    = fmaxf(m[i], rm[i]);
            const float alpha = __expf(m[i] - mn);
            m[i] = mn;
            const float p0 = __expf(s0[i] - mn);
            const float p1 = __expf(s1[i] - mn);
            Ps[ty * 4 + i][tx * 2 + 0] = p0;
            Ps[ty * 4 + i][tx * 2 + 1] = p1;
            rs[i] = p0 + p1;
            l[i] *= alpha;
            o[i][0] *= alpha; o[i][1] *= alpha; o[i][2] *= alpha; o[i][3] *= alpha;
        }
        #pragma unroll
        for (int off = 8; off; off >>= 1) {
            #pragma unroll
            for (int i = 0; i < 4; i++)
                rs[i] += __shfl_xor_sync(0xffffffffu, rs[i], off, 16);
        }
        #pragma unroll
        for (int i = 0; i < 4; i++) l[i] += rs[i];

        __syncthreads();

        #pragma unroll 8
        for (int k2 = 0; k2 < 32; k2++) {
            const float4 vv = *(const float4*)&Vs[k2][tx * 4];
            const float p0 = Ps[ty * 4 + 0][k2];
            const float p1 = Ps[ty * 4 + 1][k2];
            const float p2 = Ps[ty * 4 + 2][k2];
            const float p3 = Ps[ty * 4 + 3][k2];
            o[0][0] = fmaf(p0, vv.x, o[0][0]); o[0][1] = fmaf(p0, vv.y, o[0][1]);
            o[0][2] = fmaf(p0, vv.z, o[0][2]); o[0][3] = fmaf(p0, vv.w, o[0][3]);
            o[1][0] = fmaf(p1, vv.x, o[1][0]); o[1][1] = fmaf(p1, vv.y, o[1][1]);
            o[1][2] = fmaf(p1, vv.z, o[1][2]); o[1][3] = fmaf(p1, vv.w, o[1][3]);
            o[2][0] = fmaf(p2, vv.x, o[2][0]); o[2][1] = fmaf(p2, vv.y, o[2][1]);
            o[2][2] = fmaf(p2, vv.z, o[2][2]); o[2][3] = fmaf(p2, vv.w, o[2][3]);
            o[3][0] = fmaf(p3, vv.x, o[3][0]); o[3][1] = fmaf(p3, vv.y, o[3][1]);
            o[3][2] = fmaf(p3, vv.z, o[3][2]); o[3][3] = fmaf(p3, vv.w, o[3][3]);
        }
    }

    #pragma unroll
    for (int i = 0; i < 4; i++) {
        const float inv = 1.f / l[i];
        const float4 r = make_float4(o[i][0] * inv, o[i][1] * inv,
                                     o[i][2] * inv, o[i][3] * inv);
        *(float4*)(heads + (size_t)(b * Ss + q0 + ty * 4 + i) * Dm + h * HD + tx * 4) = r;
    }
}

// ---------------------------------------------------------------------------
// Launch
// ---------------------------------------------------------------------------
extern "C" void kernel_launch(void* const* d_in, const int* in_sizes, int n_in,
                              void* d_out, int out_size)
{
    const float* query = (const float*)d_in[0];
    const float* value = (const float*)d_in[1];
    const float* Wq    = (const float*)d_in[2];
    const float* bq    = (const float*)d_in[3];
    const float* Wkv   = (const float*)d_in[4];
    const float* bkv   = (const float*)d_in[5];
    const float* Wo    = (const float*)d_in[6];
    const float* bo    = (const float*)d_in[7];
    float* out = (float*)d_out;

    float *qbuf, *kvbuf, *hbuf;
    cudaGetSymbolAddress((void**)&qbuf,  g_q);
    cudaGetSymbolAddress((void**)&kvbuf, g_kv);
    cudaGetSymbolAddress((void**)&hbuf,  g_heads);

    cudaFuncSetAttribute(gemm_mma_kernel,
                         cudaFuncAttributeMaxDynamicSharedMemorySize, GEMM_SMEM);

    // 1) q = query @ Wq + bq        [8192,1024]
    gemm_mma_kernel<<<dim3(Dm / 128, M_ROWS / 128), NTHR, GEMM_SMEM>>>(
        query, Wq, bq, qbuf, Dm, Dm);

    // 2) kv = value @ Wkv + bkv     [8192,2048]
    gemm_mma_kernel<<<dim3(2 * Dm / 128, M_ROWS / 128), NTHR, GEMM_SMEM>>>(
        value, Wkv, bkv, kvbuf, 2 * Dm, Dm);

    // 3) heads = softmax(q k^T / sqrt(HD)) v   (per head, flash)
    flash_kernel<<<dim3(Ss / 64, Bb * Hn), 256>>>(qbuf, kvbuf, hbuf);

    // 4) out = heads @ Wo + bo      [8192,1024]
    gemm_mma_kernel<<<dim3(Dm / 128, M_ROWS / 128), NTHR, GEMM_SMEM>>>(
        hbuf, Wo, bo, out, Dm, Dm);
}

// round 16
// speedup vs baseline: 2.4114x; 1.5528x over previous
#include <cuda_runtime.h>
#include <cuda_bf16.h>
#include <cstdint>

// Problem constants
#define Dm 1024
#define Hn 16
#define HD 64
#define Bb 8
#define Ss 1024
#define M_ROWS (Bb * Ss)          // 8192

// Scratch (no runtime allocation allowed)
__device__ float g_q[(size_t)M_ROWS * Dm];        // 33.5 MB
__device__ float g_kv[(size_t)M_ROWS * 2 * Dm];   // 67 MB
__device__ float g_heads[(size_t)M_ROWS * Dm];    // 33.5 MB

// ===========================================================================
// Helpers
// ===========================================================================
#define MMA16816(c, a, b)                                                     \
    asm volatile("mma.sync.aligned.m16n8k16.row.col.f32.bf16.bf16.f32 "       \
        "{%0,%1,%2,%3}, {%4,%5,%6,%7}, {%8,%9}, {%0,%1,%2,%3};"               \
        : "+f"((c)[0]), "+f"((c)[1]), "+f"((c)[2]), "+f"((c)[3])              \
        : "r"((a)[0]), "r"((a)[1]), "r"((a)[2]), "r"((a)[3]),                 \
          "r"((b)[0]), "r"((b)[1]))

// fp32 pair -> (hi bf16 pair, lo bf16 pair) packed as uint32
__device__ __forceinline__ void split2(float x, float y, uint32_t& hi, uint32_t& lo) {
    __nv_bfloat16 hx = __float2bfloat16(x), hy = __float2bfloat16(y);
    __nv_bfloat16 lx = __float2bfloat16(x - __bfloat162float(hx));
    __nv_bfloat16 ly = __float2bfloat16(y - __bfloat162float(hy));
    hi = (uint32_t)__bfloat16_as_ushort(hx) | ((uint32_t)__bfloat16_as_ushort(hy) << 16);
    lo = (uint32_t)__bfloat16_as_ushort(lx) | ((uint32_t)__bfloat16_as_ushort(ly) << 16);
}

// ===========================================================================
// HMMA GEMM + bias (unchanged from R15 best: 128x128 tile, 512 thr, staged
// ldg->compute->sts double buffer, bf16x3)
// ===========================================================================
#define KC 32
#define PITCH 36
#define T_E (128 * PITCH)
#define STAGE_E (4 * T_E)
#define STAGE_B (STAGE_E * 2)
#define GEMM_SMEM (2 * STAGE_B)
#define NTHR 512

__global__ __launch_bounds__(NTHR)
void gemm_mma_kernel(const float* __restrict__ A, const float* __restrict__ W,
                     const float* __restrict__ bias, float* __restrict__ C,
                     int N, int K)
{
    extern __shared__ __nv_bfloat16 sm[];

    const int tid  = threadIdx.x;
    const int lane = tid & 31;
    const int warp = tid >> 5;
    const int g    = lane >> 2;
    const int tig  = lane & 3;
    const int warp_m0 = (warp >> 2) * 32;
    const int warp_n0 = (warp & 3) * 32;
    const int bm = blockIdx.y * 128;
    const int bn = blockIdx.x * 128;

    float acc[2][4][4];
    #pragma unroll
    for (int t = 0; t < 2; t++)
        #pragma unroll
        for (int u = 0; u < 4; u++)
            #pragma unroll
            for (int r = 0; r < 4; r++) acc[t][u][r] = 0.f;

    float4 ra[2];
    float2 rb[4];

    auto ldg_chunk = [&](int k0) {
        #pragma unroll
        for (int i = 0; i < 2; i++) {
            const int idx = tid + i * NTHR;
            const int row = idx >> 3;
            const int c4  = (idx & 7) * 4;
            ra[i] = *(const float4*)(A + (size_t)(bm + row) * K + k0 + c4);
        }
        #pragma unroll
        for (int i = 0; i < 4; i++) {
            const int idx = tid + i * NTHR;
            const int n  = idx & 127;
            const int kp = idx >> 7;
            const float* wp = W + (size_t)(k0 + 2 * kp) * N + bn + n;
            rb[i].x = __ldg(wp);
            rb[i].y = __ldg(wp + N);
        }
    };

    auto sts_chunk = [&](int buf) {
        __nv_bfloat16* Ah = sm + buf * STAGE_E;
        __nv_bfloat16* Al = Ah + T_E;
        __nv_bfloat16* Bh = Al + T_E;
        __nv_bfloat16* Bl = Bh + T_E;
        #pragma unroll
        for (int i = 0; i < 2; i++) {
            const int idx = tid + i * NTHR;
            const int row = idx >> 3;
            const int c4  = (idx & 7) * 4;
            uint32_t h0, l0, h1, l1;
            split2(ra[i].x, ra[i].y, h0, l0);
            split2(ra[i].z, ra[i].w, h1, l1);
            *(uint2*)(Ah + row * PITCH + c4) = make_uint2(h0, h1);
            *(uint2*)(Al + row * PITCH + c4) = make_uint2(l0, l1);
        }
        #pragma unroll
        for (int i = 0; i < 4; i++) {
            const int idx = tid + i * NTHR;
            const int n  = idx & 127;
            const int kp = idx >> 7;
            uint32_t hp, lp;
            split2(rb[i].x, rb[i].y, hp, lp);
            *(uint32_t*)(Bh + n * PITCH + 2 * kp) = hp;
            *(uint32_t*)(Bl + n * PITCH + 2 * kp) = lp;
        }
    };

    auto compute_stage = [&](int buf) {
        const __nv_bfloat16* Ah = sm + buf * STAGE_E;
        const __nv_bfloat16* Al = Ah + T_E;
        const __nv_bfloat16* Bh = Al + T_E;
        const __nv_bfloat16* Bl = Bh + T_E;

        #pragma unroll
        for (int ks = 0; ks < KC; ks += 16) {
            uint32_t af[2][4], bh[4][2], bl[4][2];
            #pragma unroll
            for (int t = 0; t < 2; t++) {
                const __nv_bfloat16* p = Ah + (warp_m0 + t * 16 + g) * PITCH + ks + tig * 2;
                af[t][0] = *(const uint32_t*)p;
                af[t][1] = *(const uint32_t*)(p + 8 * PITCH);
                af[t][2] = *(const uint32_t*)(p + 8);
                af[t][3] = *(const uint32_t*)(p + 8 * PITCH + 8);
            }
            #pragma unroll
            for (int u = 0; u < 4; u++) {
                const __nv_bfloat16* p = Bh + (warp_n0 + u * 8 + g) * PITCH + ks + tig * 2;
                bh[u][0] = *(const uint32_t*)p;
                bh[u][1] = *(const uint32_t*)(p + 8);
                const __nv_bfloat16* q = Bl + (warp_n0 + u * 8 + g) * PITCH + ks + tig * 2;
                bl[u][0] = *(const uint32_t*)q;
                bl[u][1] = *(const uint32_t*)(q + 8);
            }
            #pragma unroll
            for (int t = 0; t < 2; t++)
                #pragma unroll
                for (int u = 0; u < 4; u++)
                    MMA16816(acc[t][u], af[t], bh[u]);
            #pragma unroll
            for (int t = 0; t < 2; t++)
                #pragma unroll
                for (int u = 0; u < 4; u++)
                    MMA16816(acc[t][u], af[t], bl[u]);
            #pragma unroll
            for (int t = 0; t < 2; t++) {
                const __nv_bfloat16* p = Al + (warp_m0 + t * 16 + g) * PITCH + ks + tig * 2;
                af[t][0] = *(const uint32_t*)p;
                af[t][1] = *(const uint32_t*)(p + 8 * PITCH);
                af[t][2] = *(const uint32_t*)(p + 8);
                af[t][3] = *(const uint32_t*)(p + 8 * PITCH + 8);
            }
            #pragma unroll
            for (int t = 0; t < 2; t++)
                #pragma unroll
                for (int u = 0; u < 4; u++)
                    MMA16816(acc[t][u], af[t], bh[u]);
        }
    };

    const int NC = K / KC;
    ldg_chunk(0);
    sts_chunk(0);
    __syncthreads();

    for (int c = 0; c < NC; c++) {
        if (c + 1 < NC) ldg_chunk((c + 1) * KC);
        compute_stage(c & 1);
        if (c + 1 < NC) sts_chunk((c + 1) & 1);
        __syncthreads();
    }

    #pragma unroll
    for (int t = 0; t < 2; t++) {
        const int r0 = bm + warp_m0 + t * 16 + g;
        #pragma unroll
        for (int u = 0; u < 4; u++) {
            const int cb = bn + warp_n0 + u * 8 + tig * 2;
            const float2 bv = *(const float2*)(bias + cb);
            *(float2*)(C + (size_t)r0 * N + cb) =
                make_float2(acc[t][u][0] + bv.x, acc[t][u][1] + bv.y);
            *(float2*)(C + (size_t)(r0 + 8) * N + cb) =
                make_float2(acc[t][u][2] + bv.x, acc[t][u][3] + bv.y);
        }
    }
}

// ===========================================================================
// Flash attention on HMMA, bf16x3 split for BOTH QK^T and PV.
// Grid (S/256, B*H), 512 thr / 16 warps. Warp = 16 q-rows (m16).
// Q frags register-resident (pre-scaled); S-acc reused directly as P A-frag
// (FA-2 register trick); K natural [key][d], V transposed [d][key] in smem;
// ldg->compute->sts double buffer (R14 pattern).
// ===========================================================================
#define QROWS 256
#define TS 32                       // keys per tile
#define NTILE (Ss / TS)             // 32
#define PK 68                       // K tile pitch (elems)
#define PVT 34                      // Vt pitch (elems)
#define KT_E (TS * PK)              // 2176
#define VT_E (HD * PVT)             // 2176
#define FSTAGE_E (2 * KT_E + 2 * VT_E)   // Kh,Kl,Vh,Vl = 8704 elems

__global__ __launch_bounds__(512)
void flash_mma_kernel(const float* __restrict__ q, const float* __restrict__ kv,
                      float* __restrict__ heads)
{
    __shared__ __align__(16) __nv_bfloat16 fsm[2 * FSTAGE_E];   // 34816 B

    const int tid  = threadIdx.x;
    const int lane = tid & 31;
    const int warp = tid >> 5;
    const int g    = lane >> 2;
    const int tig  = lane & 3;
    const int bh   = blockIdx.y;
    const int b    = bh >> 4;
    const int h    = bh & 15;
    const int q0   = blockIdx.x * QROWS;
    const int rowA = q0 + warp * 16 + g;      // + 8 for second row

    // ---- Q fragments: load once, scale by 1/8, split hi/lo (32 regs) ----
    uint32_t aqh[4][4], aql[4][4];
    {
        const float* qb = q + (size_t)b * Ss * Dm + h * HD;
        #pragma unroll
        for (int ks = 0; ks < 4; ks++)
            #pragma unroll
            for (int f = 0; f < 4; f++) {
                const int r = rowA + (f & 1) * 8;
                const int d = ks * 16 + (f >> 1) * 8 + tig * 2;
                const float2 v = *(const float2*)(qb + (size_t)r * Dm + d);
                split2(v.x * 0.125f, v.y * 0.125f, aqh[ks][f], aql[ks][f]);
            }
    }

    float o[8][4];
    #pragma unroll
    for (int u = 0; u < 8; u++)
        #pragma unroll
        for (int r = 0; r < 4; r++) o[u][r] = 0.f;
    float m0 = -1e30f, m1 = -1e30f, l0 = 0.f, l1 = 0.f;

    const float* kbase = kv + (size_t)b * Ss * (2 * Dm) + h * HD;
    const float* vbase = kbase + Dm;
    const int skey = tid >> 4;          // 0..31
    const int sc4  = (tid & 15) * 4;    // 0..60

    float4 rk, rv;
    auto ldg_tile = [&](int t) {
        const size_t key = (size_t)(t * TS + skey);
        rk = *(const float4*)(kbase + key * (2 * Dm) + sc4);
        rv = *(const float4*)(vbase + key * (2 * Dm) + sc4);
    };
    auto sts_tile = [&](int bf) {
        __nv_bfloat16* Kh = fsm + bf * FSTAGE_E;
        __nv_bfloat16* Kl = Kh + KT_E;
        __nv_bfloat16* Vh = Kl + KT_E;
        __nv_bfloat16* Vl = Vh + VT_E;
        uint32_t h0, w0, h1, w1;
        split2(rk.x, rk.y, h0, w0);
        split2(rk.z, rk.w, h1, w1);
        *(uint2*)(Kh + skey * PK + sc4) = make_uint2(h0, h1);
        *(uint2*)(Kl + skey * PK + sc4) = make_uint2(w0, w1);
        const float vv[4] = {rv.x, rv.y, rv.z, rv.w};
        #pragma unroll
        for (int j = 0; j < 4; j++) {
            __nv_bfloat16 vh = __float2bfloat16(vv[j]);
            __nv_bfloat16 vl = __float2bfloat16(vv[j] - __bfloat162float(vh));
            Vh[(sc4 + j) * PVT + skey] = vh;
            Vl[(sc4 + j) * PVT + skey] = vl;
        }
    };

    auto compute_tile = [&](int bf) {
        const __nv_bfloat16* Kh = fsm + bf * FSTAGE_E;
        const __nv_bfloat16* Kl = Kh + KT_E;
        const __nv_bfloat16* Vh = Kl + KT_E;
        const __nv_bfloat16* Vl = Vh + VT_E;

        // ---- S = Q K^T (16 rows x 32 keys), 3-pass split ----
        float s[4][4];
        #pragma unroll
        for (int u = 0; u < 4; u++)
            #pragma unroll
            for (int r = 0; r < 4; r++) s[u][r] = 0.f;

        #pragma unroll
        for (int ks = 0; ks < 4; ks++) {
            uint32_t kbh[4][2], kbl[4][2];
            #pragma unroll
            for (int u = 0; u < 4; u++) {
                const __nv_bfloat16* p = Kh + (u * 8 + g) * PK + ks * 16 + tig * 2;
                kbh[u][0] = *(const uint32_t*)p;
                kbh[u][1] = *(const uint32_t*)(p + 8);
                const __nv_bfloat16* pl = Kl + (u * 8 + g) * PK + ks * 16 + tig * 2;
                kbl[u][0] = *(const uint32_t*)pl;
                kbl[u][1] = *(const uint32_t*)(pl + 8);
            }
            #pragma unroll
            for (int u = 0; u < 4; u++) MMA16816(s[u], aqh[ks], kbh[u]);
            #pragma unroll
            for (int u = 0; u < 4; u++) MMA16816(s[u], aqh[ks], kbl[u]);
            #pragma unroll
            for (int u = 0; u < 4; u++) MMA16816(s[u], aql[ks], kbh[u]);
        }

        // ---- online softmax (rows g and g+8; quad shares rows) ----
        float rm0 = s[0][0], rm1 = s[0][2];
        #pragma unroll
        for (int u = 0; u < 4; u++) {
            rm0 = fmaxf(rm0, fmaxf(s[u][0], s[u][1]));
            rm1 = fmaxf(rm1, fmaxf(s[u][2], s[u][3]));
        }
        rm0 = fmaxf(rm0, __shfl_xor_sync(0xffffffffu, rm0, 1));
        rm0 = fmaxf(rm0, __shfl_xor_sync(0xffffffffu, rm0, 2));
        rm1 = fmaxf(rm1, __shfl_xor_sync(0xffffffffu, rm1, 1));
        rm1 = fmaxf(rm1, __shfl_xor_sync(0xffffffffu, rm1, 2));

        const float mn0 = fmaxf(m0, rm0);
        const float mn1 = fmaxf(m1, rm1);
        const float a0 = __expf(m0 - mn0);
        const float a1 = __expf(m1 - mn1);
        m0 = mn0; m1 = mn1;

        uint32_t pah[2][4], pal[2][4];
        float rs0 = 0.f, rs1 = 0.f;
        #pragma unroll
        for (int kp = 0; kp < 2; kp++)
            #pragma unroll
            for (int uu = 0; uu < 2; uu++) {
                const int u = kp * 2 + uu;
                const float p0 = __expf(s[u][0] - mn0);
                const float p1 = __expf(s[u][1] - mn0);
                const float p2 = __expf(s[u][2] - mn1);
                const float p3 = __expf(s[u][3] - mn1);
                rs0 += p0 + p1;
                rs1 += p2 + p3;
                split2(p0, p1, pah[kp][uu * 2 + 0], pal[kp][uu * 2 + 0]);
                split2(p2, p3, pah[kp][uu * 2 + 1], pal[kp][uu * 2 + 1]);
            }
        rs0 += __shfl_xor_sync(0xffffffffu, rs0, 1);
        rs0 += __shfl_xor_sync(0xffffffffu, rs0, 2);
        rs1 += __shfl_xor_sync(0xffffffffu, rs1, 1);
        rs1 += __shfl_xor_sync(0xffffffffu, rs1, 2);
        l0 = l0 * a0 + rs0;
        l1 = l1 * a1 + rs1;

        #pragma unroll
        for (int u = 0; u < 8; u++) {
            o[u][0] *= a0; o[u][1] *= a0;
            o[u][2] *= a1; o[u][3] *= a1;
        }

        // ---- O += P V, 3-pass split ----
        #pragma unroll
        for (int kp = 0; kp < 2; kp++) {
            uint32_t vbh[8][2], vbl[8][2];
            #pragma unroll
            for (int u = 0; u < 8; u++) {
                const __nv_bfloat16* p = Vh + (u * 8 + g) * PVT + kp * 16 + tig * 2;
                vbh[u][0] = *(const uint32_t*)p;
                vbh[u][1] = *(const uint32_t*)(p + 8);
                const __nv_bfloat16* pl = Vl + (u * 8 + g) * PVT + kp * 16 + tig * 2;
                vbl[u][0] = *(const uint32_t*)pl;
                vbl[u][1] = *(const uint32_t*)(pl + 8);
            }
            #pragma unroll
            for (int u = 0; u < 8; u++) MMA16816(o[u], pah[kp], vbh[u]);
            #pragma unroll
            for (int u = 0; u < 8; u++) MMA16816(o[u], pah[kp], vbl[u]);
            #pragma unroll
            for (int u = 0; u < 8; u++) MMA16816(o[u], pal[kp], vbh[u]);
        }
    };

    ldg_tile(0);
    sts_tile(0);
    __syncthreads();

    for (int t = 0; t < NTILE; t++) {
        if (t + 1 < NTILE) ldg_tile(t + 1);
        compute_tile(t & 1);
        if (t + 1 < NTILE) sts_tile((t + 1) & 1);
        __syncthreads();
    }

    // ---- normalize + write heads ----
    const float i0 = 1.f / l0;
    const float i1 = 1.f / l1;
    float* hb = heads + (size_t)b * Ss * Dm + h * HD;
    #pragma unroll
    for (int u = 0; u < 8; u++) {
        const int d = u * 8 + tig * 2;
        *(float2*)(hb + (size_t)rowA * Dm + d) =
            make_float2(o[u][0] * i0, o[u][1] * i0);
        *(float2*)(hb + (size_t)(rowA + 8) * Dm + d) =
            make_float2(o[u][2] * i1, o[u][3] * i1);
    }
}

// ---------------------------------------------------------------------------
// Launch
// ---------------------------------------------------------------------------
extern "C" void kernel_launch(void* const* d_in, const int* in_sizes, int n_in,
                              void* d_out, int out_size)
{
    const float* query = (const float*)d_in[0];
    const float* value = (const float*)d_in[1];
    const float* Wq    = (const float*)d_in[2];
    const float* bq    = (const float*)d_in[3];
    const float* Wkv   = (const float*)d_in[4];
    const float* bkv   = (const float*)d_in[5];
    const float* Wo    = (const float*)d_in[6];
    const float* bo    = (const float*)d_in[7];
    float* out = (float*)d_out;

    float *qbuf, *kvbuf, *hbuf;
    cudaGetSymbolAddress((void**)&qbuf,  g_q);
    cudaGetSymbolAddress((void**)&kvbuf, g_kv);
    cudaGetSymbolAddress((void**)&hbuf,  g_heads);

    cudaFuncSetAttribute(gemm_mma_kernel,
                         cudaFuncAttributeMaxDynamicSharedMemorySize, GEMM_SMEM);

    // 1) q = query @ Wq + bq        [8192,1024]
    gemm_mma_kernel<<<dim3(Dm / 128, M_ROWS / 128), NTHR, GEMM_SMEM>>>(
        query, Wq, bq, qbuf, Dm, Dm);

    // 2) kv = value @ Wkv + bkv     [8192,2048]
    gemm_mma_kernel<<<dim3(2 * Dm / 128, M_ROWS / 128), NTHR, GEMM_SMEM>>>(
        value, Wkv, bkv, kvbuf, 2 * Dm, Dm);

    // 3) heads = softmax(q k^T / sqrt(HD)) v   (flash on tensor cores)
    flash_mma_kernel<<<dim3(Ss / QROWS, Bb * Hn), 512>>>(qbuf, kvbuf, hbuf);

    // 4) out = heads @ Wo + bo      [8192,1024]
    gemm_mma_kernel<<<dim3(Dm / 128, M_ROWS / 128), NTHR, GEMM_SMEM>>>(
        hbuf, Wo, bo, out, Dm, Dm);
}